// round 1
// baseline (speedup 1.0000x reference)
#include <cuda_runtime.h>
#include <math.h>

// Problem constants (from reference): B=1, N=50000, K=32, D=128
#define D_DIM 128
#define K_NBR 32
#define THREADS 128

__global__ __launch_bounds__(THREADS, 1)
void attn_encoder_kernel(const float* __restrict__ h_n,
                         const float* __restrict__ neighbor,
                         float* __restrict__ out,
                         int n_nodes)
{
    __shared__ float nb_sh[K_NBR * D_DIM];   // 16384 B
    __shared__ float h_sh[D_DIM];            // 512 B
    __shared__ float sc_sh[K_NBR];           // scores
    __shared__ float at_sh[K_NBR];           // attn weights

    const int node = blockIdx.x;
    if (node >= n_nodes) return;

    const int tid  = threadIdx.x;
    const int wid  = tid >> 5;
    const int lane = tid & 31;

    // ---- Stage tile: 32*128 floats = 1024 float4, 128 threads -> 8 each ----
    {
        const float4* src = reinterpret_cast<const float4*>(neighbor + (size_t)node * K_NBR * D_DIM);
        float4* dst = reinterpret_cast<float4*>(nb_sh);
        #pragma unroll
        for (int i = 0; i < 8; ++i)
            dst[tid + i * THREADS] = src[tid + i * THREADS];
        // h_n: 128 floats = 32 float4 -> first 32 threads
        if (tid < D_DIM / 4) {
            const float4* hs = reinterpret_cast<const float4*>(h_n + (size_t)node * D_DIM);
            reinterpret_cast<float4*>(h_sh)[tid] = hs[tid];
        }
    }
    __syncthreads();

    // ---- Scores: warp w handles neighbors k = w*8 .. w*8+7 ----
    {
        #pragma unroll
        for (int kk = 0; kk < 8; ++kk) {
            const int k = wid * 8 + kk;
            const float* nbk = nb_sh + k * D_DIM;
            float p = 0.f;
            #pragma unroll
            for (int j = 0; j < 4; ++j) {
                const int d = lane + j * 32;
                p = fmaf(nbk[d], h_sh[d], p);
            }
            // warp reduce
            #pragma unroll
            for (int off = 16; off > 0; off >>= 1)
                p += __shfl_xor_sync(0xffffffffu, p, off);
            if (lane == 0)
                sc_sh[k] = p * 0.08838834764831845f;  // 1/sqrt(128)
        }
    }
    __syncthreads();

    // ---- Softmax over 32 scores (warp 0) ----
    if (wid == 0) {
        float s = sc_sh[lane];
        float m = s;
        #pragma unroll
        for (int off = 16; off > 0; off >>= 1)
            m = fmaxf(m, __shfl_xor_sync(0xffffffffu, m, off));
        float e = __expf(s - m);
        float sum = e;
        #pragma unroll
        for (int off = 16; off > 0; off >>= 1)
            sum += __shfl_xor_sync(0xffffffffu, sum, off);
        at_sh[lane] = e / sum;
    }
    __syncthreads();

    // ---- Aggregate: thread d computes sum_k attn[k]*nb[k][d], add residual ----
    {
        float agg = 0.f;
        #pragma unroll
        for (int k = 0; k < K_NBR; ++k)
            agg = fmaf(at_sh[k], nb_sh[k * D_DIM + tid], agg);
        out[(size_t)node * D_DIM + tid] = h_sh[tid] + agg;
    }
}

extern "C" void kernel_launch(void* const* d_in, const int* in_sizes, int n_in,
                              void* d_out, int out_size)
{
    const float* h_n      = (const float*)d_in[0];   // (B,N,D)
    const float* neighbor = (const float*)d_in[1];   // (B,N,K,D)
    float* out = (float*)d_out;

    const int n_nodes = in_sizes[0] / D_DIM;  // B*N = 50000

    attn_encoder_kernel<<<n_nodes, THREADS>>>(h_n, neighbor, out, n_nodes);
}

// round 2
// speedup vs baseline: 1.0597x; 1.0597x over previous
#include <cuda_runtime.h>
#include <math.h>

// B=1, N=50000, K=32, D=128, fp32
#define D_DIM 128
#define K_NBR 32
#define THREADS 128

__global__ __launch_bounds__(THREADS, 8)
void attn_encoder_kernel(const float* __restrict__ h_n,
                         const float* __restrict__ neighbor,
                         float* __restrict__ out,
                         int n_nodes)
{
    __shared__ float sc_sh[K_NBR];           // raw scores
    __shared__ float at_sh[K_NBR];           // attn weights
    __shared__ float red[4 * D_DIM];         // per-warp partial aggregates (2 KB)

    const int node = blockIdx.x;
    if (node >= n_nodes) return;

    const int tid  = threadIdx.x;
    const int w    = tid >> 5;    // warp: owns neighbors 8w..8w+7
    const int lane = tid & 31;    // lane: owns d-chunk [4*lane, 4*lane+3]

    // ---- Load neighbor tile straight into registers (no smem staging) ----
    // neighbor[node][k][d]: as float4, row k starts at node*1024 + k*32.
    const float4* nb4 = reinterpret_cast<const float4*>(neighbor);
    const float4* nbp = nb4 + (size_t)node * (K_NBR * D_DIM / 4) + (w * 8) * (D_DIM / 4) + lane;

    float4 nb[8];
    #pragma unroll
    for (int kk = 0; kk < 8; ++kk)
        nb[kk] = nbp[kk * (D_DIM / 4)];      // 8 independent coalesced LDG.128

    const float4 hv = reinterpret_cast<const float4*>(h_n)[(size_t)node * (D_DIM / 4) + lane];

    // ---- Scores: dot(h, nb_k) per neighbor, warp butterfly reduce ----
    #pragma unroll
    for (int kk = 0; kk < 8; ++kk) {
        float p = fmaf(nb[kk].x, hv.x,
                  fmaf(nb[kk].y, hv.y,
                  fmaf(nb[kk].z, hv.z, nb[kk].w * hv.w)));
        #pragma unroll
        for (int off = 16; off > 0; off >>= 1)
            p += __shfl_xor_sync(0xffffffffu, p, off);
        if (lane == kk)
            sc_sh[w * 8 + kk] = p * 0.08838834764831845f;  // 1/sqrt(128)
    }
    __syncthreads();

    // ---- Softmax over 32 scores (warp 0) ----
    if (w == 0) {
        float s = sc_sh[lane];
        float m = s;
        #pragma unroll
        for (int off = 16; off > 0; off >>= 1)
            m = fmaxf(m, __shfl_xor_sync(0xffffffffu, m, off));
        float e = __expf(s - m);
        float sum = e;
        #pragma unroll
        for (int off = 16; off > 0; off >>= 1)
            sum += __shfl_xor_sync(0xffffffffu, sum, off);
        at_sh[lane] = e / sum;
    }
    __syncthreads();

    // ---- Aggregate in registers over this warp's 8 neighbors ----
    float4 acc = make_float4(0.f, 0.f, 0.f, 0.f);
    #pragma unroll
    for (int kk = 0; kk < 8; ++kk) {
        const float a = at_sh[w * 8 + kk];
        acc.x = fmaf(a, nb[kk].x, acc.x);
        acc.y = fmaf(a, nb[kk].y, acc.y);
        acc.z = fmaf(a, nb[kk].z, acc.z);
        acc.w = fmaf(a, nb[kk].w, acc.w);
    }
    // partial per warp -> smem (conflict-free STS.128)
    reinterpret_cast<float4*>(red)[w * 32 + lane] = acc;
    __syncthreads();

    // ---- Cross-warp sum + residual, thread tid handles scalar d = tid ----
    const float r = red[0 * D_DIM + tid] + red[1 * D_DIM + tid]
                  + red[2 * D_DIM + tid] + red[3 * D_DIM + tid];
    out[(size_t)node * D_DIM + tid] = h_n[(size_t)node * D_DIM + tid] + r;
}

extern "C" void kernel_launch(void* const* d_in, const int* in_sizes, int n_in,
                              void* d_out, int out_size)
{
    const float* h_n      = (const float*)d_in[0];   // (B,N,D)
    const float* neighbor = (const float*)d_in[1];   // (B,N,K,D)
    float* out = (float*)d_out;

    const int n_nodes = in_sizes[0] / D_DIM;  // B*N = 50000

    attn_encoder_kernel<<<n_nodes, THREADS>>>(h_n, neighbor, out, n_nodes);
}